// round 5
// baseline (speedup 1.0000x reference)
#include <cuda_runtime.h>

// Siamese LSTM: V=100000, E=300, H=15, T=2048.
// Kernel 1: embedding gather + input projection (fully parallel)
//   pre[seq][t][j] = b_ih[j] + b_hh[j] + sum_e emb[tok[t],e] * W_ih[j,e]
// Kernel 2: one warp per sequence runs the 2048-step recurrence entirely in
//   registers + warp shuffles; fused MLP head at the end.

#define T_LEN 2048
#define HID   15
#define G4    60     // 4*HID
#define E4    75     // 300/4

// scratch: 2 * 2048 * 60 floats (~983 KB), L2-resident between kernels
__device__ float g_pre[2][T_LEN * G4];

// ---------------------------------------------------------------------------
// Kernel 1: gather + input projection. One block per (seq, t), 64 threads,
// thread j computes gate preactivation j via float4 dot over E=300.
// W_ih (72 KB) stays L1-resident across the ~27 blocks each SM processes.
// ---------------------------------------------------------------------------
__global__ void __launch_bounds__(64) proj_kernel(
    const int*   __restrict__ s1,
    const int*   __restrict__ s2,
    const float* __restrict__ emb,
    const float* __restrict__ W_ih,
    const float* __restrict__ b_ih,
    const float* __restrict__ b_hh)
{
    const int bx  = blockIdx.x;       // 0..4095
    const int seq = bx >> 11;
    const int t   = bx & (T_LEN - 1);
    const int j   = threadIdx.x;
    if (j >= G4) return;

    const int tok = (seq ? s2 : s1)[t];
    const float4* e4 = reinterpret_cast<const float4*>(emb) + (long long)tok * E4;
    const float4* w4 = reinterpret_cast<const float4*>(W_ih) + j * E4;

    float a0 = b_ih[j] + b_hh[j];
    float a1 = 0.f, a2 = 0.f, a3 = 0.f;
    #pragma unroll 5
    for (int k = 0; k < E4; k++) {
        float4 e = __ldg(&e4[k]);
        float4 w = __ldg(&w4[k]);
        a0 = fmaf(e.x, w.x, a0);
        a1 = fmaf(e.y, w.y, a1);
        a2 = fmaf(e.z, w.z, a2);
        a3 = fmaf(e.w, w.w, a3);
    }
    g_pre[seq][t * G4 + j] = (a0 + a1) + (a2 + a3);
}

// fast, numerically-safe sigmoid / tanh built on MUFU (EX2 + RCP), ~2^-21 rel err
__device__ __forceinline__ float fsig(float x) {
    // x -> -inf: expf -> inf, rcp -> 0  => 0.  x -> +inf: 1/(1+0) = 1.
    return __fdividef(1.f, 1.f + __expf(-x));
}
__device__ __forceinline__ float ftanh(float x) {
    // 1 - 2/(e^{2x}+1): x->-inf => 1 - 2/1 = -1; x->+inf => 1 - 0 = 1. No NaNs.
    return 1.f - __fdividef(2.f, __expf(2.f * x) + 1.f);
}

// ---------------------------------------------------------------------------
// Kernel 2: the sequential scan. 1 block, 64 threads. Warp w handles sequence
// w. Lane j (j<30) computes gate j (i/f block) and gate j+30 (g/o block).
// Lane k (k<15) owns h_k, c_k. h broadcast via shfl; f,o fetched with 2 shfls.
// Distance-2 register prefetch of preactivations hides L2 latency.
// Fused MLP head at the end (warp 0).
// ---------------------------------------------------------------------------
__global__ void __launch_bounds__(64) lstm_kernel(
    const float* __restrict__ W_hh,
    const float* __restrict__ h1_0, const float* __restrict__ c1_0,
    const float* __restrict__ h2_0, const float* __restrict__ c2_0,
    const float* __restrict__ W1,   const float* __restrict__ b1,
    const float* __restrict__ W2,   const float* __restrict__ b2,
    float* __restrict__ out)
{
    __shared__ float s_v[2][HID];
    __shared__ float s_hid[25];

    const int warp = threadIdx.x >> 5;
    const int lane = threadIdx.x & 31;
    const int j    = (lane < 30) ? lane : 29;   // clamp idle lanes in-bounds

    const float* __restrict__ pre = g_pre[warp];

    // per-lane recurrent weight rows (gate j and gate j+30)
    float w0[HID], w1[HID];
    #pragma unroll
    for (int k = 0; k < HID; k++) {
        w0[k] = W_hh[j * HID + k];
        w1[k] = W_hh[(j + 30) * HID + k];
    }

    float h = 0.f, c = 0.f;
    if (lane < HID) {
        h = warp ? h2_0[lane] : h1_0[lane];
        c = warp ? c2_0[lane] : c1_0[lane];
    }

    // prefetch preactivations for t = 0, 1
    float pb0[2], pb1[2];
    pb0[0] = pre[j];           pb1[0] = pre[30 + j];
    pb0[1] = pre[G4 + j];      pb1[1] = pre[G4 + 30 + j];

    const unsigned FULL = 0xffffffffu;
    const bool lo = (lane < HID);

    #pragma unroll 2
    for (int t = 0; t < T_LEN; t++) {
        float p0 = pb0[t & 1], p1 = pb1[t & 1];
        if (t + 2 < T_LEN) {                     // prefetch t+2
            pb0[t & 1] = pre[(t + 2) * G4 + j];
            pb1[t & 1] = pre[(t + 2) * G4 + 30 + j];
        }

        // gates: a0 = preact + h . W_hh[row j], a1 = ... row j+30
        float a0 = p0, a0b = 0.f, a1 = p1, a1b = 0.f;
        #pragma unroll
        for (int k = 0; k < HID; k++) {
            float hk = __shfl_sync(FULL, h, k);
            if (k & 1) { a0b = fmaf(hk, w0[k], a0b); a1b = fmaf(hk, w1[k], a1b); }
            else       { a0  = fmaf(hk, w0[k], a0 ); a1  = fmaf(hk, w1[k], a1 ); }
        }
        a0 += a0b; a1 += a1b;

        // activations: a0 -> sigmoid (i for lanes<15, f for 15..29)
        //              a1 -> tanh (g, lanes<15) via 2*sig(2x)-1, sigmoid (o) else
        float s0  = fsig(a0);
        float s1v = fsig(lo ? 2.f * a1 : a1);
        float go  = lo ? (2.f * s1v - 1.f) : s1v;     // g or o

        // lanes 0..14 fetch f_k and o_k from lane 15+k
        float f = __shfl_sync(FULL, s0, lane + 15);
        float o = __shfl_sync(FULL, go, lane + 15);

        // state update (meaningful on lanes < 15 only)
        c = fmaf(f, c, s0 * go);         // f*c + i*g
        h = o * ftanh(c);
    }

    if (lane < HID) s_v[warp][lane] = h;
    __syncthreads();

    // ---- MLP head (warp 0) ----
    if (warp == 0) {
        if (lane < 25) {
            const float* wr = W1 + lane * 75;
            float acc = b1[lane];
            #pragma unroll
            for (int k = 0; k < HID; k++) {
                float v1 = s_v[0][k], v2 = s_v[1][k];
                acc = fmaf(wr[k],      v1,               acc);
                acc = fmaf(wr[15 + k], fabsf(v1 - v2),   acc);
                acc = fmaf(wr[30 + k], v2,               acc);
                acc = fmaf(wr[45 + k], v1 * v2,          acc);
                acc = fmaf(wr[60 + k], 0.5f * (v1 + v2), acc);
            }
            s_hid[lane] = acc;
        }
        __syncwarp();
        if (lane < 2) {
            float acc = b2[lane];
            #pragma unroll
            for (int k = 0; k < 25; k++)
                acc = fmaf(W2[lane * 25 + k], s_hid[k], acc);
            out[lane] = acc;
        }
    }
}

extern "C" void kernel_launch(void* const* d_in, const int* in_sizes, int n_in,
                              void* d_out, int out_size)
{
    const int*   s1   = (const int*)  d_in[0];
    const int*   s2   = (const int*)  d_in[1];
    const float* emb  = (const float*)d_in[2];
    const float* W_ih = (const float*)d_in[3];
    const float* W_hh = (const float*)d_in[4];
    const float* b_ih = (const float*)d_in[5];
    const float* b_hh = (const float*)d_in[6];
    const float* W1   = (const float*)d_in[7];
    const float* b1   = (const float*)d_in[8];
    const float* W2   = (const float*)d_in[9];
    const float* b2   = (const float*)d_in[10];
    const float* h1_0 = (const float*)d_in[11];
    const float* c1_0 = (const float*)d_in[12];
    const float* h2_0 = (const float*)d_in[13];
    const float* c2_0 = (const float*)d_in[14];
    float* out = (float*)d_out;

    proj_kernel<<<2 * T_LEN, 64>>>(s1, s2, emb, W_ih, b_ih, b_hh);
    lstm_kernel<<<1, 64>>>(W_hh, h1_0, c1_0, h2_0, c2_0, W1, b1, W2, b2, out);
}

// round 8
// speedup vs baseline: 1.2778x; 1.2778x over previous
#include <cuda_runtime.h>

// Siamese LSTM: V=100000, E=300, H=15, T=2048.
// Kernel 1: embedding gather + input projection (fully parallel).
// Kernel 2: one warp per sequence, 2048-step recurrence in registers +
//   warp shuffles, MUFU.TANH activations, fused MLP head.

#define T_LEN 2048
#define HID   15
#define G4    60     // 4*HID
#define E4    75     // 300/4
#define PAD   4      // prefetch distance padding (timesteps)

// scratch: 2 * (2048+4) * 60 floats (~985 KB), L2-resident between kernels
__device__ float g_pre[2][(T_LEN + PAD) * G4];

// ---------------------------------------------------------------------------
// Kernel 1: gather + input projection. One block per (seq, t), 64 threads,
// thread j computes gate preactivation j via float4 dot over E=300.
// ---------------------------------------------------------------------------
__global__ void __launch_bounds__(64) proj_kernel(
    const int*   __restrict__ s1,
    const int*   __restrict__ s2,
    const float* __restrict__ emb,
    const float* __restrict__ W_ih,
    const float* __restrict__ b_ih,
    const float* __restrict__ b_hh)
{
    const int bx  = blockIdx.x;       // 0..4095
    const int seq = bx >> 11;
    const int t   = bx & (T_LEN - 1);
    const int j   = threadIdx.x;
    if (j >= G4) return;

    const int tok = (seq ? s2 : s1)[t];
    const float4* e4 = reinterpret_cast<const float4*>(emb) + (long long)tok * E4;
    const float4* w4 = reinterpret_cast<const float4*>(W_ih) + j * E4;

    float a0 = b_ih[j] + b_hh[j];
    float a1 = 0.f, a2 = 0.f, a3 = 0.f;
    #pragma unroll 5
    for (int k = 0; k < E4; k++) {
        float4 e = __ldg(&e4[k]);
        float4 w = __ldg(&w4[k]);
        a0 = fmaf(e.x, w.x, a0);
        a1 = fmaf(e.y, w.y, a1);
        a2 = fmaf(e.z, w.z, a2);
        a3 = fmaf(e.w, w.w, a3);
    }
    g_pre[seq][t * G4 + j] = (a0 + a1) + (a2 + a3);
}

// single-MUFU tanh (MUFU.TANH, sm_75+)
__device__ __forceinline__ float tanh_mufu(float x) {
    float y;
    asm("tanh.approx.f32 %0, %1;" : "=f"(y) : "f"(x));
    return y;
}

// ---------------------------------------------------------------------------
// Kernel 2: sequential scan. 1 block, 64 threads; warp w = sequence w.
// Lane j<30 computes gate rows j (i/f, sigmoid) and j+30 (g: tanh on lanes
// <15, o: sigmoid on lanes 15..29). Lane k<15 owns h_k, c_k.
// sigmoid(x) = fma(0.5, tanh(0.5x), 0.5). Distance-4 register prefetch.
// ---------------------------------------------------------------------------
__global__ void __launch_bounds__(64) lstm_kernel(
    const float* __restrict__ W_hh,
    const float* __restrict__ h1_0, const float* __restrict__ c1_0,
    const float* __restrict__ h2_0, const float* __restrict__ c2_0,
    const float* __restrict__ W1,   const float* __restrict__ b1,
    const float* __restrict__ W2,   const float* __restrict__ b2,
    float* __restrict__ out)
{
    __shared__ float s_v[2][HID];
    __shared__ float s_hid[25];

    const int warp = threadIdx.x >> 5;
    const int lane = threadIdx.x & 31;
    const int j    = (lane < 30) ? lane : 29;   // clamp idle lanes in-bounds

    const float* __restrict__ pre = g_pre[warp];

    // per-lane recurrent weight rows (gate j and gate j+30)
    float w0[HID], w1[HID];
    #pragma unroll
    for (int k = 0; k < HID; k++) {
        w0[k] = W_hh[j * HID + k];
        w1[k] = W_hh[(j + 30) * HID + k];
    }

    float h = 0.f, c = 0.f;
    if (lane < HID) {
        h = warp ? h2_0[lane] : h1_0[lane];
        c = warp ? c2_0[lane] : c1_0[lane];
    }

    // activation-select constants for the a1 (g/o) path:
    //   lanes < 15 : g = tanh(a1)            -> m1=1,   m2=1,   m3=0
    //   lanes >= 15: o = sigmoid(a1)         -> m1=0.5, m2=0.5, m3=0.5
    const bool  lo = (lane < HID);
    const float m1 = lo ? 1.0f : 0.5f;
    const float m2 = m1;
    const float m3 = lo ? 0.0f : 0.5f;

    // distance-4 prefetch buffers
    float pb0[PAD], pb1[PAD];
    #pragma unroll
    for (int u = 0; u < PAD; u++) {
        pb0[u] = pre[u * G4 + j];
        pb1[u] = pre[u * G4 + 30 + j];
    }
    const float* pf = pre + PAD * G4;

    const unsigned FULL = 0xffffffffu;

    #pragma unroll 4
    for (int t = 0; t < T_LEN; t++) {
        const int ph = t & (PAD - 1);
        float p0 = pb0[ph], p1 = pb1[ph];
        pb0[ph] = pf[j];                 // prefetch t+4 (padded buffer)
        pb1[ph] = pf[30 + j];
        pf += G4;

        // gates: a0 = pre + h . W_hh[j],  a1 = pre + h . W_hh[j+30]
        float a0 = p0, a0b = 0.f, a1 = p1, a1b = 0.f;
        #pragma unroll
        for (int k = 0; k < HID; k++) {
            float hk = __shfl_sync(FULL, h, k);
            if (k & 1) { a0b = fmaf(hk, w0[k], a0b); a1b = fmaf(hk, w1[k], a1b); }
            else       { a0  = fmaf(hk, w0[k], a0 ); a1  = fmaf(hk, w1[k], a1 ); }
        }
        a0 += a0b; a1 += a1b;

        // activations (one MUFU.TANH each)
        float s0 = fmaf(0.5f, tanh_mufu(0.5f * a0), 0.5f);  // i (lanes<15) / f
        float go = fmaf(m2, tanh_mufu(a1 * m1), m3);        // g (lanes<15) / o

        // lanes 0..14 fetch f_k and o_k from lane 15+k
        float f = __shfl_sync(FULL, s0, lane + 15);
        float o = __shfl_sync(FULL, go, lane + 15);

        // state update (meaningful on lanes < 15 only)
        c = fmaf(f, c, s0 * go);         // f*c + i*g
        h = o * tanh_mufu(c);
    }

    if (lane < HID) s_v[warp][lane] = h;
    __syncthreads();

    // ---- MLP head (warp 0) ----
    if (warp == 0) {
        if (lane < 25) {
            const float* wr = W1 + lane * 75;
            float acc = b1[lane];
            #pragma unroll
            for (int k = 0; k < HID; k++) {
                float v1 = s_v[0][k], v2 = s_v[1][k];
                acc = fmaf(wr[k],      v1,               acc);
                acc = fmaf(wr[15 + k], fabsf(v1 - v2),   acc);
                acc = fmaf(wr[30 + k], v2,               acc);
                acc = fmaf(wr[45 + k], v1 * v2,          acc);
                acc = fmaf(wr[60 + k], 0.5f * (v1 + v2), acc);
            }
            s_hid[lane] = acc;
        }
        __syncwarp();
        if (lane < 2) {
            float acc = b2[lane];
            #pragma unroll
            for (int k = 0; k < 25; k++)
                acc = fmaf(W2[lane * 25 + k], s_hid[k], acc);
            out[lane] = acc;
        }
    }
}

extern "C" void kernel_launch(void* const* d_in, const int* in_sizes, int n_in,
                              void* d_out, int out_size)
{
    const int*   s1   = (const int*)  d_in[0];
    const int*   s2   = (const int*)  d_in[1];
    const float* emb  = (const float*)d_in[2];
    const float* W_ih = (const float*)d_in[3];
    const float* W_hh = (const float*)d_in[4];
    const float* b_ih = (const float*)d_in[5];
    const float* b_hh = (const float*)d_in[6];
    const float* W1   = (const float*)d_in[7];
    const float* b1   = (const float*)d_in[8];
    const float* W2   = (const float*)d_in[9];
    const float* b2   = (const float*)d_in[10];
    const float* h1_0 = (const float*)d_in[11];
    const float* c1_0 = (const float*)d_in[12];
    const float* h2_0 = (const float*)d_in[13];
    const float* c2_0 = (const float*)d_in[14];
    float* out = (float*)d_out;

    proj_kernel<<<2 * T_LEN, 64>>>(s1, s2, emb, W_ih, b_ih, b_hh);
    lstm_kernel<<<1, 64>>>(W_hh, h1_0, c1_0, h2_0, c2_0, W1, b1, W2, b2, out);
}